// round 6
// baseline (speedup 1.0000x reference)
#include <cuda_runtime.h>
#include <cuda_bf16.h>
#include <cstdint>

// ---------------- device scratch (globals — allowed) ----------------
// Pre-tiled, pre-swizzled operand blocks for single-bulk-copy staging.
__device__ __align__(128) __nv_bfloat16 g_Ea[781UL * 32 * 4096];  // [mtile][chunk] 8KB blocks
__device__ __align__(128) __nv_bfloat16 g_Wb[8 * 32 * 8192];      // [head][chunk] 16KB blocks

namespace {

constexpr int  kSamples = 16384;
constexpr long kRows    = 98304;
constexpr int  STEPS    = 256;       // 8 heads * 32 chunks (kc=32)
constexpr int  STAGE    = 24576;     // A 8KB + B 16KB
constexpr int  BOFF     = 8192;
constexpr uint32_t QKO   = 73728;    // 3 stages end
constexpr uint32_t BIASO = 205312;   // 128*257*4 after QKO
constexpr uint32_t SCO   = 206336;
constexpr uint32_t GATO  = 209360;
constexpr uint32_t MBARO = 209872;
constexpr int  SMEM_TOTAL = 209920;
constexpr int  QKS = 257;

__device__ __forceinline__ uint32_t smem_u32(const void* p) {
  return (uint32_t)__cvta_generic_to_shared(p);
}
__device__ __forceinline__ void ldsm4(uint32_t* r, uint32_t addr) {
  asm volatile("ldmatrix.sync.aligned.m8n8.x4.shared.b16 {%0,%1,%2,%3}, [%4];"
               : "=r"(r[0]), "=r"(r[1]), "=r"(r[2]), "=r"(r[3]) : "r"(addr));
}
__device__ __forceinline__ void mma_bf16(float* d, const uint32_t* a, const uint32_t* b) {
  asm volatile(
      "mma.sync.aligned.m16n8k16.row.col.f32.bf16.bf16.f32 "
      "{%0,%1,%2,%3}, {%4,%5,%6,%7}, {%8,%9}, {%0,%1,%2,%3};\n"
      : "+f"(d[0]), "+f"(d[1]), "+f"(d[2]), "+f"(d[3])
      : "r"(a[0]), "r"(a[1]), "r"(a[2]), "r"(a[3]), "r"(b[0]), "r"(b[1]));
}
__device__ __forceinline__ void bulk_g2s(uint32_t dst, const void* src, uint32_t bytes,
                                         uint32_t mbar) {
  asm volatile(
      "cp.async.bulk.shared::cta.global.mbarrier::complete_tx::bytes [%0], [%1], %2, [%3];"
      :: "r"(dst), "l"(src), "r"(bytes), "r"(mbar) : "memory");
}
__device__ __forceinline__ void mbar_init(uint32_t a, uint32_t cnt) {
  asm volatile("mbarrier.init.shared.b64 [%0], %1;" :: "r"(a), "r"(cnt) : "memory");
}
__device__ __forceinline__ void mbar_expect_tx(uint32_t a, uint32_t bytes) {
  asm volatile("mbarrier.arrive.expect_tx.shared.b64 _, [%0], %1;"
               :: "r"(a), "r"(bytes) : "memory");
}
__device__ __forceinline__ void mbar_wait(uint32_t a, uint32_t phase) {
  asm volatile(
      "{\n .reg .pred P1;\n"
      "WL_%=:\n"
      " mbarrier.try_wait.parity.acquire.cta.shared::cta.b64 P1, [%0], %1, 0x989680;\n"
      " @P1 bra.uni WD_%=;\n"
      " bra.uni WL_%=;\n"
      "WD_%=:\n}"
      :: "r"(a), "r"(phase) : "memory");
}

// swizzled offset within a tile block: physical row p (128B), 16B unit u
__device__ __forceinline__ uint32_t swz(int p, int u) {
  return (uint32_t)(p * 128 + ((u * 16) ^ ((p & 7) << 4)));
}

}  // namespace

// ---------------- pre-pass: tiled+swizzled A scratch ----------------
__global__ void conv_ea_kernel(const float* __restrict__ emb) {
  const int bx = blockIdx.x;             // m*32 + c, m<781
  const int m = bx >> 5, c = bx & 31;
  const int tid = threadIdx.x;           // 512
  const int r = tid >> 2, ch = tid & 3;  // logical row 0..127, 16B unit 0..3
  const int p = r & 63, hi = r >> 6;     // packed: rows r and r+64 share phys row
  char* dst = (char*)g_Ea + ((size_t)bx << 13) + swz(p, hi * 4 + ch);
  const long gr = (long)m * 126 + r;
  uint4 out = {0u, 0u, 0u, 0u};
  if (r < 126 && gr < kRows) {
    const float* s = emb + gr * 1024 + c * 32 + ch * 8;
    float4 f0 = *(const float4*)s;
    float4 f1 = *(const float4*)(s + 4);
    __nv_bfloat162 v0 = __floats2bfloat162_rn(f0.x, f0.y);
    __nv_bfloat162 v1 = __floats2bfloat162_rn(f0.z, f0.w);
    __nv_bfloat162 v2 = __floats2bfloat162_rn(f1.x, f1.y);
    __nv_bfloat162 v3 = __floats2bfloat162_rn(f1.z, f1.w);
    out.x = *(uint32_t*)&v0; out.y = *(uint32_t*)&v1;
    out.z = *(uint32_t*)&v2; out.w = *(uint32_t*)&v3;
  }
  *(uint4*)dst = out;
}

// ---------------- pre-pass: tiled+swizzled B scratch ----------------
__global__ void conv_wb_kernel(const float* __restrict__ Wq, const float* __restrict__ Wk) {
  const int bx = blockIdx.x;             // h*32 + c
  const int h = bx >> 5, c = bx & 31;
  const int tid = threadIdx.x;           // 1024
  const int n = tid >> 2, ch = tid & 3;  // logical n 0..255, unit 0..3
  const int p = n & 127, hi = n >> 7;
  char* dst = (char*)g_Wb + ((size_t)bx << 14) + swz(p, hi * 4 + ch);
  const float* W = (n < 128) ? Wq : Wk;
  const int col = h * 128 + (n & 127);
  const int k0 = c * 32 + ch * 8;
  __nv_bfloat16 v[8];
#pragma unroll
  for (int t = 0; t < 8; t++) v[t] = __float2bfloat16(W[(long)(k0 + t) * 1024 + col]);
  *(uint4*)dst = *(uint4*)v;
}

// ---------------- main fused kernel ----------------
__global__ void __launch_bounds__(512, 1)
attn_main_kernel(const float* __restrict__ emb, const float* __restrict__ ac,
                 const float* __restrict__ bk, const float* __restrict__ bq,
                 const float* __restrict__ Wg, const float* __restrict__ bg,
                 float* __restrict__ ctx, float* __restrict__ att) {
  extern __shared__ char smc[];
  const uint32_t sb = smem_u32(smc);
  float* qk     = (float*)(smc + QKO);
  float* bia    = (float*)(smc + BIASO);
  float* sc     = (float*)(smc + SCO);
  float* gate_s = (float*)(smc + GATO);

  const int tid  = threadIdx.x;
  const int lane = tid & 31;
  const int warp = tid >> 5;
  const int mw   = warp >> 2, nw = warp & 3;
  const int lr   = lane >> 2, lc = lane & 3;
  const int mtile = blockIdx.x;
  const int sbase = mtile * 21;

  if (tid == 0) {
    mbar_init(sb + MBARO + 0, 1);
    mbar_init(sb + MBARO + 8, 1);
    mbar_init(sb + MBARO + 16, 1);
  }
  __syncthreads();

  auto issue = [&](int t2) {
    const int hh = t2 >> 5, cc = t2 & 31, sl = t2 % 3;
    const uint32_t mb = sb + MBARO + sl * 8;
    mbar_expect_tx(mb, 24576u);
    bulk_g2s(sb + sl * STAGE, (const char*)g_Ea + ((size_t)(mtile * 32 + cc) << 13),
             8192u, mb);
    bulk_g2s(sb + sl * STAGE + BOFF, (const char*)g_Wb + ((size_t)(hh * 32 + cc) << 14),
             16384u, mb);
  };
  if (tid == 0) { issue(0); issue(1); issue(2); }

  // ---- gate: g[s][j] = ac[s] . Wg[:,j] + bg[j]
  if (tid < 126) {
    const int s = tid / 6, j = tid % 6;
    const int sg = sbase + s;
    float g = 0.f;
    if (sg < kSamples) {
      const float* ap = ac + (long)sg * 128;
      g = bg[j];
#pragma unroll 8
      for (int c = 0; c < 128; c++) g = fmaf(ap[c], Wg[c * 6 + j], g);
    }
    gate_s[tid] = g;
  }

  // ---- per-lane ldmatrix constants (packed-row swizzled layout)
  const int gq = lane >> 3, li = lane & 7;
  const int arow0 = mw * 32 + (gq & 1) * 8 + li;
  const int arow1 = arow0 + 16;
  const uint32_t aAdr0 = (uint32_t)((arow0 & 63) * 128), aXor0 = (uint32_t)((arow0 & 7) << 4);
  const uint32_t aAdr1 = (uint32_t)((arow1 & 63) * 128), aXor1 = (uint32_t)((arow1 & 7) << 4);
  const uint32_t aHiU0 = (uint32_t)((arow0 >> 6) * 4 + (gq >> 1));
  const uint32_t aHiU1 = (uint32_t)((arow1 >> 6) * 4 + (gq >> 1));
  uint32_t bAdr[4], bXor[4], bHiU[4];
#pragma unroll
  for (int nt = 0; nt < 4; nt++) {
    const int brow = nw * 64 + nt * 16 + (gq >> 1) * 8 + li;
    bAdr[nt] = (uint32_t)(BOFF + (brow & 127) * 128);
    bXor[nt] = (uint32_t)((brow & 7) << 4);
    bHiU[nt] = (uint32_t)((brow >> 7) * 4 + (gq & 1));
  }

  const float kInvSqrt = 0.08838834764831845f;  // 1/sqrt(128)
  float acc[2][8][4];

  for (int t = 0; t < STEPS; t++) {
    const int head = t >> 5, c = t & 31;
    if (c == 0) {
#pragma unroll
      for (int a0 = 0; a0 < 2; a0++)
#pragma unroll
        for (int a1 = 0; a1 < 8; a1++)
#pragma unroll
          for (int a2 = 0; a2 < 4; a2++) acc[a0][a1][a2] = 0.f;
      if (tid < 256)
        bia[tid] = (tid < 128) ? bq[head * 128 + tid] : bk[head * 128 + tid - 128];
    }

    mbar_wait(sb + MBARO + (t % 3) * 8, (uint32_t)((t / 3) & 1));
    const uint32_t stb = sb + (uint32_t)((t % 3) * STAGE);

#pragma unroll
    for (int ks = 0; ks < 2; ks++) {
      uint32_t a0[4], a1[4];
      ldsm4(a0, stb + aAdr0 + ((((aHiU0 + ks * 2) << 4)) ^ aXor0));
      ldsm4(a1, stb + aAdr1 + ((((aHiU1 + ks * 2) << 4)) ^ aXor1));
#pragma unroll
      for (int nt = 0; nt < 4; nt++) {
        uint32_t b[4];
        ldsm4(b, stb + bAdr[nt] + ((((bHiU[nt] + ks * 2) << 4)) ^ bXor[nt]));
        mma_bf16(acc[0][nt * 2],     a0, b);
        mma_bf16(acc[0][nt * 2 + 1], a0, b + 2);
        mma_bf16(acc[1][nt * 2],     a1, b);
        mma_bf16(acc[1][nt * 2 + 1], a1, b + 2);
      }
    }
    __syncthreads();                 // all warps done with slot t%3
    if (tid == 0 && t + 3 < STEPS) issue(t + 3);

    if (c == 31) {
      // ---- epilogue for this head (stages untouched; DMA keeps running)
#pragma unroll
      for (int mt = 0; mt < 2; mt++)
#pragma unroll
        for (int nt = 0; nt < 8; nt++) {
          const int r0 = mw * 32 + mt * 16 + lr;
          const int c0 = nw * 64 + nt * 8 + 2 * lc;
          qk[r0 * QKS + c0]           = acc[mt][nt][0] + bia[c0];
          qk[r0 * QKS + c0 + 1]       = acc[mt][nt][1] + bia[c0 + 1];
          qk[(r0 + 8) * QKS + c0]     = acc[mt][nt][2] + bia[c0];
          qk[(r0 + 8) * QKS + c0 + 1] = acc[mt][nt][3] + bia[c0 + 1];
        }
      __syncthreads();

      for (int s = warp; s < 21; s += 16) {
        const int sg = sbase + s;
        if (sg >= kSamples) continue;
        float qv[6][4], kv[6][4];
#pragma unroll
        for (int i = 0; i < 6; i++) {
          const float* qp = qk + (s * 6 + i) * QKS + lane;
#pragma unroll
          for (int u = 0; u < 4; u++) {
            qv[i][u] = qp[32 * u];
            kv[i][u] = qp[128 + 32 * u];
          }
        }
#pragma unroll
        for (int i = 0; i < 6; i++)
#pragma unroll
          for (int j = 0; j < 6; j++) {
            float p = qv[i][0] * kv[j][0] + qv[i][1] * kv[j][1]
                    + qv[i][2] * kv[j][2] + qv[i][3] * kv[j][3];
#pragma unroll
            for (int o = 16; o > 0; o >>= 1) p += __shfl_xor_sync(0xffffffffu, p, o);
            if (lane == 0) sc[s * 36 + i * 6 + j] = p;
          }
      }
      __syncthreads();

      if (tid < 126) {
        const int s = tid / 6, i = tid % 6;
        const int sg = sbase + s;
        if (sg < kSamples) {
          float l[6], mx = -1e30f;
#pragma unroll
          for (int j = 0; j < 6; j++) {
            l[j] = sc[s * 36 + i * 6 + j] * kInvSqrt * gate_s[s * 6 + j];
            mx = fmaxf(mx, l[j]);
          }
          float sum = 0.f;
#pragma unroll
          for (int j = 0; j < 6; j++) { l[j] = expf(l[j] - mx); sum += l[j]; }
          const float rcp = 1.f / sum;
          float* ao = att + (((long)sg * 8 + head) * 6 + i) * 6;
#pragma unroll
          for (int j = 0; j < 6; j++) {
            const float a = l[j] * rcp;
            ao[j] = a;
            sc[s * 36 + i * 6 + j] = a;
          }
        }
      }
      __syncthreads();

      for (int idx = tid; idx < 21 * 128; idx += 512) {
        const int s = idx >> 7;
        const int cc = idx & 127;
        const int sg = sbase + s;
        if (sg >= kSamples) continue;
        const float* ep = emb + (long)sg * 6 * 1024 + head * 128 + cc;
        float e[6];
#pragma unroll
        for (int j = 0; j < 6; j++) e[j] = ep[(long)j * 1024];
#pragma unroll
        for (int i = 0; i < 6; i++) {
          float v = 0.f;
#pragma unroll
          for (int j = 0; j < 6; j++) v = fmaf(sc[s * 36 + i * 6 + j], e[j], v);
          ctx[((long)sg * 6 + i) * 1024 + head * 128 + cc] = v;
        }
      }
      __syncthreads();
    }
  }
}

extern "C" void kernel_launch(void* const* d_in, const int* in_sizes, int n_in,
                              void* d_out, int out_size) {
  (void)in_sizes; (void)n_in; (void)out_size;
  const float* emb = (const float*)d_in[0];
  const float* ac  = (const float*)d_in[1];
  const float* Wk  = (const float*)d_in[2];
  const float* bk  = (const float*)d_in[3];
  const float* Wq  = (const float*)d_in[4];
  const float* bq  = (const float*)d_in[5];
  const float* Wg  = (const float*)d_in[6];
  const float* bg  = (const float*)d_in[7];

  float* ctx = (float*)d_out;
  float* att = ctx + kRows * 1024L;

  conv_ea_kernel<<<781 * 32, 512>>>(emb);
  conv_wb_kernel<<<8 * 32, 1024>>>(Wq, Wk);

  cudaFuncSetAttribute(attn_main_kernel,
                       cudaFuncAttributeMaxDynamicSharedMemorySize, SMEM_TOTAL);
  attn_main_kernel<<<781, 512, SMEM_TOTAL>>>(emb, ac, bk, bq, Wg, bg, ctx, att);
}

// round 7
// speedup vs baseline: 1.3983x; 1.3983x over previous
#include <cuda_runtime.h>
#include <cuda_bf16.h>
#include <cstdint>

// ---------------- device scratch (globals — allowed) ----------------
__device__ __nv_bfloat16 g_Ebf[98304UL * 1024];   // E in bf16, row-major
__device__ __nv_bfloat16 g_Wt[8 * 256 * 1024];    // [head][n (Q0..127|K128..255)][k]
__device__ float         g_gate[16384 * 6];

namespace {

constexpr int  kSamples = 16384;
constexpr long kRows    = 98304;               // 16384*6
constexpr int  CHUNKS   = 16;                  // K=1024 / 64
constexpr int  STAGE    = 49152;               // A 16KB + B 32KB
constexpr int  BOFF     = 16384;               // B within stage
constexpr uint32_t AUX  = 147456;              // after 3 stages
constexpr uint32_t BIASO= AUX;                 // 256 f32
constexpr uint32_t SCO  = AUX + 1024;          // 756 f32
constexpr int  SMEM_TOTAL = 152576;
constexpr int  QKS = 257;                      // qk stride (floats); qk aliases stages

__device__ __forceinline__ uint32_t smem_u32(const void* p) {
  return (uint32_t)__cvta_generic_to_shared(p);
}
__device__ __forceinline__ void cpa16(uint32_t dst, const void* src, int sz) {
  asm volatile("cp.async.cg.shared.global [%0], [%1], 16, %2;\n"
               :: "r"(dst), "l"(src), "r"(sz));
}
__device__ __forceinline__ void ldsm4(uint32_t* r, uint32_t addr) {
  asm volatile("ldmatrix.sync.aligned.m8n8.x4.shared.b16 {%0,%1,%2,%3}, [%4];"
               : "=r"(r[0]), "=r"(r[1]), "=r"(r[2]), "=r"(r[3]) : "r"(addr));
}
__device__ __forceinline__ void mma_bf16(float* d, const uint32_t* a, const uint32_t* b) {
  asm volatile(
      "mma.sync.aligned.m16n8k16.row.col.f32.bf16.bf16.f32 "
      "{%0,%1,%2,%3}, {%4,%5,%6,%7}, {%8,%9}, {%0,%1,%2,%3};\n"
      : "+f"(d[0]), "+f"(d[1]), "+f"(d[2]), "+f"(d[3])
      : "r"(a[0]), "r"(a[1]), "r"(a[2]), "r"(a[3]), "r"(b[0]), "r"(b[1]));
}

}  // namespace

// ---------------- pre-pass kernels ----------------
__global__ void conv_e_kernel(const float* __restrict__ emb) {
  const long total = kRows * 1024 / 8;
  for (long i = blockIdx.x * 256L + threadIdx.x; i < total; i += (long)gridDim.x * 256) {
    const float4* s = (const float4*)emb + i * 2;
    float4 a = s[0], b = s[1];
    __nv_bfloat162* o = (__nv_bfloat162*)g_Ebf + i * 4;
    o[0] = __floats2bfloat162_rn(a.x, a.y);
    o[1] = __floats2bfloat162_rn(a.z, a.w);
    o[2] = __floats2bfloat162_rn(b.x, b.y);
    o[3] = __floats2bfloat162_rn(b.z, b.w);
  }
}

__global__ void conv_w_kernel(const float* __restrict__ Wq, const float* __restrict__ Wk) {
  const int idx = blockIdx.x * 256 + threadIdx.x;  // 262144 total
  const int h  = idx >> 15;
  const int n  = (idx >> 7) & 255;
  const int k0 = (idx & 127) * 8;
  const float* W = (n < 128) ? Wq : Wk;
  const int col = h * 128 + (n & 127);
  __nv_bfloat16* o = g_Wt + ((long)(h * 256 + n)) * 1024 + k0;
#pragma unroll
  for (int t = 0; t < 8; t++) o[t] = __float2bfloat16(W[(long)(k0 + t) * 1024 + col]);
}

__global__ void gate_kernel(const float* __restrict__ ac, const float* __restrict__ Wg,
                            const float* __restrict__ bg) {
  const int idx = blockIdx.x * 256 + threadIdx.x;  // 98304
  const int s = idx / 6, j = idx % 6;
  const float* ap = ac + (long)s * 128;
  float g = bg[j];
#pragma unroll 8
  for (int c = 0; c < 128; c++) g = fmaf(ap[c], Wg[c * 6 + j], g);
  g_gate[idx] = g;
}

// ---------------- main fused kernel: one (mtile, head) per CTA ----------------
__global__ void __launch_bounds__(512, 1)
attn_main_kernel(const float* __restrict__ emb, const float* __restrict__ bk,
                 const float* __restrict__ bq, float* __restrict__ ctx,
                 float* __restrict__ att) {
  extern __shared__ char smc[];
  const uint32_t sb = smem_u32(smc);
  float* qk  = (float*)smc;              // 128 x 257 f32, aliases stage area post-GEMM
  float* bia = (float*)(smc + BIASO);
  float* sc  = (float*)(smc + SCO);

  const int tid  = threadIdx.x;
  const int lane = tid & 31;
  const int warp = tid >> 5;
  const int mw   = warp >> 2;   // 0..3 (32-row band)
  const int nw   = warp & 3;    // 0..3 (64-col band)
  const int lr   = lane >> 2;   // 0..3? no: 0..7
  const int lc   = lane & 3;

  const int head  = blockIdx.x & 7;
  const int mtile = blockIdx.x >> 3;
  const int sbase = mtile * 21;
  const long rbase = (long)sbase * 6;

  if (tid < 256)
    bia[tid] = (tid < 128) ? bq[head * 128 + tid] : bk[head * 128 + tid - 128];

  // ---- per-lane ldmatrix address precompute (within-stage offsets)
  const int gq = lane >> 3, li = lane & 7;
  const int arow = mw * 32 + (gq & 1) * 8 + li;     // + mt*16
  const uint32_t aKb  = (uint32_t)((gq >> 1) * 16);
  const uint32_t aXor = (uint32_t)((arow & 7) << 4);
  const uint32_t aOff0 = (uint32_t)(arow * 128);
  const uint32_t aOff1 = aOff0 + 16 * 128;
  const int brow = nw * 64 + (gq >> 1) * 8 + li;    // + nt*16
  const uint32_t bKb  = (uint32_t)((gq & 1) * 16);
  const uint32_t bXor = (uint32_t)((brow & 7) << 4);
  const uint32_t bOffB = (uint32_t)(BOFF + brow * 128);

  auto loadA = [&](int c, int stage) {
    const int kc0 = c * 64;
#pragma unroll
    for (int it = 0; it < 2; it++) {
      const int v = tid + it * 512;         // 0..1023
      const int r = v >> 3, ch = v & 7;
      const long gr = rbase + r;
      const bool ok = gr < kRows;
      const uint32_t dst = sb + stage * STAGE + (uint32_t)(r * 128) +
                           (uint32_t)((ch * 16) ^ ((r & 7) << 4));
      cpa16(dst, g_Ebf + (ok ? gr : 0) * 1024 + kc0 + ch * 8, ok ? 16 : 0);
    }
  };
  auto loadB = [&](int c, int stage) {
    const int kc0 = c * 64;
#pragma unroll
    for (int it = 0; it < 4; it++) {
      const int v = tid + it * 512;         // 0..2047
      const int n = v >> 3, ch = v & 7;
      const uint32_t dst = sb + stage * STAGE + BOFF + (uint32_t)(n * 128) +
                           (uint32_t)((ch * 16) ^ ((n & 7) << 4));
      cpa16(dst, g_Wt + (long)(head * 256 + n) * 1024 + kc0 + ch * 8, 16);
    }
  };

  float acc[2][8][4];
#pragma unroll
  for (int a0 = 0; a0 < 2; a0++)
#pragma unroll
    for (int a1 = 0; a1 < 8; a1++)
#pragma unroll
      for (int a2 = 0; a2 < 4; a2++) acc[a0][a1][a2] = 0.f;

  loadA(0, 0); loadB(0, 0);
  asm volatile("cp.async.commit_group;" ::: "memory");
  loadA(1, 1); loadB(1, 1);
  asm volatile("cp.async.commit_group;" ::: "memory");

  for (int c = 0; c < CHUNKS; c++) {
    if (c < CHUNKS - 1) asm volatile("cp.async.wait_group 1;" ::: "memory");
    else                asm volatile("cp.async.wait_group 0;" ::: "memory");
    __syncthreads();

    if (c + 2 < CHUNKS) {
      loadA(c + 2, (c + 2) % 3);
      loadB(c + 2, (c + 2) % 3);
      asm volatile("cp.async.commit_group;" ::: "memory");
    }

    const uint32_t stb = sb + (uint32_t)((c % 3) * STAGE);
#pragma unroll
    for (int ks = 0; ks < 4; ks++) {
      uint32_t a0[4], a1[4];
      const uint32_t akb = (uint32_t)(ks * 32) + aKb;
      ldsm4(a0, stb + aOff0 + (akb ^ aXor));
      ldsm4(a1, stb + aOff1 + (akb ^ aXor));
      const uint32_t bkb = (uint32_t)(ks * 32) + bKb;
#pragma unroll
      for (int nt = 0; nt < 4; nt++) {
        uint32_t b[4];
        ldsm4(b, stb + bOffB + (uint32_t)(nt * 16 * 128) + (bkb ^ bXor));
        mma_bf16(acc[0][nt * 2],     a0, b);
        mma_bf16(acc[0][nt * 2 + 1], a0, b + 2);
        mma_bf16(acc[1][nt * 2],     a1, b);
        mma_bf16(acc[1][nt * 2 + 1], a1, b + 2);
      }
    }
  }
  __syncthreads();   // all mma done; stage area reusable as qk

  // ---- dump Q|K tile (+bias) into union smem
#pragma unroll
  for (int mt = 0; mt < 2; mt++)
#pragma unroll
    for (int nt = 0; nt < 8; nt++) {
      const int r0 = mw * 32 + mt * 16 + lr;
      const int c0 = nw * 64 + nt * 8 + 2 * lc;
      qk[r0 * QKS + c0]           = acc[mt][nt][0] + bia[c0];
      qk[r0 * QKS + c0 + 1]       = acc[mt][nt][1] + bia[c0 + 1];
      qk[(r0 + 8) * QKS + c0]     = acc[mt][nt][2] + bia[c0];
      qk[(r0 + 8) * QKS + c0 + 1] = acc[mt][nt][3] + bia[c0 + 1];
    }
  __syncthreads();

  const float kInvSqrt = 0.08838834764831845f;  // 1/sqrt(128)

  // ---- scores: one warp per sample
  for (int s = warp; s < 21; s += 16) {
    const int sg = sbase + s;
    if (sg >= kSamples) continue;
    float qv[6][4], kv[6][4];
#pragma unroll
    for (int i = 0; i < 6; i++) {
      const float* qp = qk + (s * 6 + i) * QKS + lane;
#pragma unroll
      for (int u = 0; u < 4; u++) {
        qv[i][u] = qp[32 * u];
        kv[i][u] = qp[128 + 32 * u];
      }
    }
#pragma unroll
    for (int i = 0; i < 6; i++)
#pragma unroll
      for (int j = 0; j < 6; j++) {
        float p = qv[i][0] * kv[j][0] + qv[i][1] * kv[j][1]
                + qv[i][2] * kv[j][2] + qv[i][3] * kv[j][3];
#pragma unroll
        for (int o = 16; o > 0; o >>= 1) p += __shfl_xor_sync(0xffffffffu, p, o);
        if (lane == 0) sc[s * 36 + i * 6 + j] = p;
      }
  }
  __syncthreads();

  // ---- gated softmax; write attention; keep A in smem
  if (tid < 126) {
    const int s = tid / 6, i = tid % 6;
    const int sg = sbase + s;
    if (sg < kSamples) {
      float l[6], mx = -1e30f;
#pragma unroll
      for (int j = 0; j < 6; j++) {
        l[j] = sc[s * 36 + i * 6 + j] * kInvSqrt * g_gate[sg * 6 + j];
        mx = fmaxf(mx, l[j]);
      }
      float sum = 0.f;
#pragma unroll
      for (int j = 0; j < 6; j++) { l[j] = expf(l[j] - mx); sum += l[j]; }
      const float rcp = 1.f / sum;
      float* ao = att + (((long)sg * 8 + head) * 6 + i) * 6;
#pragma unroll
      for (int j = 0; j < 6; j++) {
        const float a = l[j] * rcp;
        ao[j] = a;
        sc[s * 36 + i * 6 + j] = a;
      }
    }
  }
  __syncthreads();

  // ---- context: ctx[6s+i, head*128+cc] = sum_j A[i][j] * E[6s+j, head*128+cc]
  for (int idx = tid; idx < 21 * 128; idx += 512) {
    const int s = idx >> 7;
    const int cc = idx & 127;
    const int sg = sbase + s;
    if (sg >= kSamples) continue;
    const float* ep = emb + (long)sg * 6 * 1024 + head * 128 + cc;
    float e[6];
#pragma unroll
    for (int j = 0; j < 6; j++) e[j] = ep[(long)j * 1024];
#pragma unroll
    for (int i = 0; i < 6; i++) {
      float v = 0.f;
#pragma unroll
      for (int j = 0; j < 6; j++) v = fmaf(sc[s * 36 + i * 6 + j], e[j], v);
      ctx[((long)sg * 6 + i) * 1024 + head * 128 + cc] = v;
    }
  }
}

extern "C" void kernel_launch(void* const* d_in, const int* in_sizes, int n_in,
                              void* d_out, int out_size) {
  (void)in_sizes; (void)n_in; (void)out_size;
  const float* emb = (const float*)d_in[0];
  const float* ac  = (const float*)d_in[1];
  const float* Wk  = (const float*)d_in[2];
  const float* bk  = (const float*)d_in[3];
  const float* Wq  = (const float*)d_in[4];
  const float* bq  = (const float*)d_in[5];
  const float* Wg  = (const float*)d_in[6];
  const float* bg  = (const float*)d_in[7];

  float* ctx = (float*)d_out;
  float* att = ctx + kRows * 1024L;

  conv_e_kernel<<<8192, 256>>>(emb);
  conv_w_kernel<<<1024, 256>>>(Wq, Wk);
  gate_kernel<<<384, 256>>>(ac, Wg, bg);

  cudaFuncSetAttribute(attn_main_kernel,
                       cudaFuncAttributeMaxDynamicSharedMemorySize, SMEM_TOTAL);
  attn_main_kernel<<<781 * 8, 512, SMEM_TOTAL>>>(emb, bk, bq, ctx, att);
}